// round 5
// baseline (speedup 1.0000x reference)
#include <cuda_runtime.h>

#define NN 4
#define HH 480
#define WW 640

// Scratch (static device arrays; no allocation anywhere). All NHWC float4.
__device__ float4 g_b1[NN * HH * WW];   // ping
__device__ float4 g_b2[NN * HH * WW];   // pong / theta
__device__ float4 g_xt[NN * HH * WW];   // x packed NHWC (c=0..2, lane w = 0)

// ---------------------------------------------------------------------------
// Kernel 0: pack x [N,3,H,W] -> NHWC float4 (4th lane zero)
// ---------------------------------------------------------------------------
__global__ void __launch_bounds__(256) pack_x_kernel(const float* __restrict__ x) {
    int idx = blockIdx.x * 256 + threadIdx.x;
    const int total = NN * HH * WW;
    if (idx >= total) return;
    int n  = idx / (HH * WW);
    int hw = idx - n * (HH * WW);
    const float* xb = x + (size_t)n * 3 * HH * WW + hw;
    float4 v;
    v.x = __ldg(&xb[0]);
    v.y = __ldg(&xb[HH * WW]);
    v.z = __ldg(&xb[2 * HH * WW]);
    v.w = 0.f;
    g_xt[idx] = v;
}

// ---------------------------------------------------------------------------
// 5x5 conv, pad 2, NHWC float4 in/out (channels in lanes -> no ic loop).
// Block 32x8; thread computes 4 ADJACENT px (x = x0 + 4*tx + 0..3).
// Tile: 12 x 132 float4 with halo. Weights float4-over-ic per [ky][kx][oc].
// SRC: 0 = g_xt, 1 = g_b1, 2 = g_b2.  DST: 1 = g_b1, 2 = g_b2.
// ---------------------------------------------------------------------------
template <int IC, int SRC, int DST>
__global__ void __launch_bounds__(256) conv5_kernel(
    const float* __restrict__ w, const float* __restrict__ b)
{
    __shared__ float4 tile4[12][132];
    __shared__ float4 wsh[5][5][4];   // [ky][kx][oc] -> lanes = ic 0..3
    __shared__ float4 b4s;

    const int tx  = threadIdx.x;
    const int ty  = threadIdx.y;
    const int tid = ty * 32 + tx;
    const int x0  = blockIdx.x * 128;
    const int y0  = blockIdx.y * 8;
    const int n   = blockIdx.z;

    const float4* in = (SRC == 0) ? g_xt : (SRC == 1) ? g_b1 : g_b2;
    float4* out      = (DST == 1) ? g_b1 : g_b2;

    // weights: src layout [OC=4][IC][5][5] -> wsh[ky][kx][oc] lanes over ic
    if (tid < 100) {
        int oc = tid / 25;
        int k  = tid - oc * 25;        // ky*5+kx
        float4 wv;
        wv.x = __ldg(&w[(oc * IC + 0) * 25 + k]);
        wv.y = __ldg(&w[(oc * IC + 1) * 25 + k]);
        wv.z = __ldg(&w[(oc * IC + 2) * 25 + k]);
        wv.w = (IC == 4) ? __ldg(&w[(oc * IC + 3) * 25 + k]) : 0.f;
        wsh[k / 5][k % 5][oc] = wv;
    }
    if (tid == 0)
        b4s = make_float4(__ldg(&b[0]), __ldg(&b[1]), __ldg(&b[2]), __ldg(&b[3]));

    // input tile with halo: rows y0-2..y0+9, cols x0-2..x0+129 (float4 elems)
    const float4* inb = in + (size_t)n * HH * WW;
    for (int i = tid; i < 12 * 132; i += 256) {
        int r  = i / 132;
        int c  = i - r * 132;
        int gy = y0 + r - 2;
        int gx = x0 + c - 2;
        float4 v = make_float4(0.f, 0.f, 0.f, 0.f);
        if (gy >= 0 && gy < HH && gx >= 0 && gx < WW)
            v = __ldg(&inb[gy * WW + gx]);
        tile4[r][c] = v;
    }
    __syncthreads();

    // acc[p] = float4 over oc for pixel p
    float4 acc[4];
#pragma unroll
    for (int p = 0; p < 4; ++p) acc[p] = b4s;

#pragma unroll 1
    for (int ky = 0; ky < 5; ++ky) {
        const float4* rowp = &tile4[ty + ky][4 * tx];
        float4 v[8];
#pragma unroll
        for (int j = 0; j < 8; ++j) v[j] = rowp[j];
#pragma unroll
        for (int kx = 0; kx < 5; ++kx) {
            const float4 w0 = wsh[ky][kx][0];
            const float4 w1 = wsh[ky][kx][1];
            const float4 w2 = wsh[ky][kx][2];
            const float4 w3 = wsh[ky][kx][3];
#pragma unroll
            for (int p = 0; p < 4; ++p) {
                const float4 xv = v[p + kx];
                acc[p].x += xv.x * w0.x + xv.y * w0.y + xv.z * w0.z + xv.w * w0.w;
                acc[p].y += xv.x * w1.x + xv.y * w1.y + xv.z * w1.z + xv.w * w1.w;
                acc[p].z += xv.x * w2.x + xv.y * w2.y + xv.z * w2.z + xv.w * w2.w;
                acc[p].w += xv.x * w3.x + xv.y * w3.y + xv.z * w3.z + xv.w * w3.w;
            }
        }
    }

    const int y  = y0 + ty;
    const int xb = x0 + 4 * tx;
    float4* o4 = out + (size_t)n * HH * WW + y * WW + xb;
#pragma unroll
    for (int p = 0; p < 4; ++p) o4[p] = acc[p];
}

// ---------------------------------------------------------------------------
// Fused: grid build + bilinear grid_sample + stride-3 3x3 conv epilogue.
// theta in NHWC float4 (g_b2). x in NHWC float4 (g_xt).
// Thread map: tx -> h (gathers coalesced along x columns), ty -> w.
// ---------------------------------------------------------------------------
__device__ __forceinline__ float4 fetch4(const float4* __restrict__ b, int x, int y) {
    if ((unsigned)x < (unsigned)WW && (unsigned)y < (unsigned)HH)
        return __ldg(&b[y * WW + x]);
    return make_float4(0.f, 0.f, 0.f, 0.f);
}

__global__ void __launch_bounds__(256) stn_sample_kernel(
    const float* __restrict__ wr, const float* __restrict__ br,
    float* __restrict__ out)
{
    __shared__ float wsh[81];
    __shared__ float bsh[3];
    __shared__ float so[3][32][9];

    const int tx  = threadIdx.x;
    const int ty  = threadIdx.y;
    const int tid = ty * 32 + tx;
    if (tid < 81) wsh[tid] = __ldg(&wr[tid]);
    if (tid < 3)  bsh[tid] = __ldg(&br[tid]);
    __syncthreads();

    const int h0 = blockIdx.x * 32;
    const int w0 = blockIdx.y * 8;
    const int n  = blockIdx.z;
    const int h  = h0 + tx;
    const int w  = w0 + ty;

    const float4* tb = g_b2 + (size_t)n * HH * WW;
    const float4* xb = g_xt + (size_t)n * HH * WW;

    const float4 th = __ldg(&tb[h * WW + w]);

    const float yy = -1.f + 2.f * (float)h / (float)(HH - 1);
    const float xx = -1.f + 2.f * (float)w / (float)(WW - 1);

    float acc0 = 0.f, acc1 = 0.f, acc2 = 0.f;

#pragma unroll
    for (int i = 0; i < 3; ++i) {
        const float lyv = (float)(i - 1) * (3.0f / (float)HH);
#pragma unroll
        for (int j = 0; j < 3; ++j) {
            const float lxv = (float)(j - 1) * (3.0f / (float)WW);
            const float gx = yy + th.x * lyv + th.y * lxv;   // grid[...,0] (x coord)
            const float gy = xx + th.z * lyv + th.w * lxv;   // grid[...,1] (y coord)
            const float ix = ((gx + 1.0f) * (float)WW - 1.0f) * 0.5f;
            const float iy = ((gy + 1.0f) * (float)HH - 1.0f) * 0.5f;
            const float ix0 = floorf(ix);
            const float iy0 = floorf(iy);
            const float wx1 = ix - ix0;
            const float wy1 = iy - iy0;
            const float wx0 = 1.0f - wx1;
            const float wy0 = 1.0f - wy1;
            const int xi = (int)ix0;
            const int yi = (int)iy0;

            const float4 v00 = fetch4(xb, xi,     yi);
            const float4 v10 = fetch4(xb, xi + 1, yi);
            const float4 v01 = fetch4(xb, xi,     yi + 1);
            const float4 v11 = fetch4(xb, xi + 1, yi + 1);

            const float w00 = wx0 * wy0, w10 = wx1 * wy0;
            const float w01 = wx0 * wy1, w11 = wx1 * wy1;

            const float vx = v00.x * w00 + v10.x * w10 + v01.x * w01 + v11.x * w11;
            const float vy = v00.y * w00 + v10.y * w10 + v01.y * w01 + v11.y * w11;
            const float vz = v00.z * w00 + v10.z * w10 + v01.z * w01 + v11.z * w11;

            const int k = i * 3 + j;
            acc0 += wsh[0 * 27 + k] * vx + wsh[0 * 27 + 9 + k] * vy + wsh[0 * 27 + 18 + k] * vz;
            acc1 += wsh[1 * 27 + k] * vx + wsh[1 * 27 + 9 + k] * vy + wsh[1 * 27 + 18 + k] * vz;
            acc2 += wsh[2 * 27 + k] * vx + wsh[2 * 27 + 9 + k] * vy + wsh[2 * 27 + 18 + k] * vz;
        }
    }

    so[0][tx][ty] = acc0 + bsh[0];
    so[1][tx][ty] = acc1 + bsh[1];
    so[2][tx][ty] = acc2 + bsh[2];
    __syncthreads();

    for (int e = tid; e < 3 * 32 * 8; e += 256) {
        int oc = e >> 8;
        int r  = (e >> 3) & 31;
        int c  = e & 7;
        out[((size_t)(n * 3 + oc) * HH + h0 + r) * WW + w0 + c] = so[oc][r][c];
    }
}

// ---------------------------------------------------------------------------
extern "C" void kernel_launch(void* const* d_in, const int* in_sizes, int n_in,
                              void* d_out, int out_size)
{
    const float* x  = (const float*)d_in[0];
    const float* w1 = (const float*)d_in[1];
    const float* b1 = (const float*)d_in[2];
    const float* w2 = (const float*)d_in[3];
    const float* b2 = (const float*)d_in[4];
    const float* w3 = (const float*)d_in[5];
    const float* b3 = (const float*)d_in[6];
    const float* w4 = (const float*)d_in[7];
    const float* b4 = (const float*)d_in[8];
    const float* wr = (const float*)d_in[9];
    const float* br = (const float*)d_in[10];
    float* out = (float*)d_out;

    const dim3 cb(32, 8);
    const dim3 cg(WW / 128, HH / 8, NN);     // (5, 60, 4)

    pack_x_kernel<<<(NN * HH * WW + 255) / 256, 256>>>(x);

    conv5_kernel<3, 0, 1><<<cg, cb>>>(w1, b1);   // xt -> b1
    conv5_kernel<4, 1, 2><<<cg, cb>>>(w2, b2);   // b1 -> b2
    conv5_kernel<4, 2, 1><<<cg, cb>>>(w3, b3);   // b2 -> b1
    conv5_kernel<4, 1, 2><<<cg, cb>>>(w4, b4);   // b1 -> b2 (theta NHWC4)

    const dim3 sb(32, 8);
    const dim3 sg(HH / 32, WW / 8, NN);      // (15, 80, 4)
    stn_sample_kernel<<<sg, sb>>>(wr, br, out);
}